// round 5
// baseline (speedup 1.0000x reference)
#include <cuda_runtime.h>
#include <cuda_bf16.h>

// Problem constants (fixed by the dataset)
#define D 64
#define NT 4
#define N_NODES_MAX 50000

// Scratch accumulator: [agg_s: N*64 floats][agg_v: N*192 floats] = N*256 floats.
// float4-typed to guarantee 16B alignment for red.global.add.v4.f32.
__device__ float4 g_agg4[N_NODES_MAX * 64];   // 50000*256 floats = 51.2 MB

// ---------------------------------------------------------------------------
// Kernel 1: zero the accumulator
// ---------------------------------------------------------------------------
__global__ void zero_agg_kernel(int n4) {
    int i = blockIdx.x * blockDim.x + threadIdx.x;
    if (i < n4) g_agg4[i] = make_float4(0.f, 0.f, 0.f, 0.f);
}

// ---------------------------------------------------------------------------
// Kernel 2: edge scatter.  Each thread handles one float4 of one edge's
// message (64 float4s per edge: 16 for x-row, 48 for vec-rows) and issues a
// vectorized global reduction into the dst accumulator.
// ---------------------------------------------------------------------------
__global__ void scatter_kernel(const float4* __restrict__ x4,
                               const float4* __restrict__ v4,
                               const int*    __restrict__ src,
                               const int*    __restrict__ dst,
                               int n_edges, int n_nodes) {
    int i = blockIdx.x * blockDim.x + threadIdx.x;
    int total = n_edges * 64;
    if (i >= total) return;
    int e = i >> 6;
    int j = i & 63;
    int s = __ldg(src + e);
    int d = __ldg(dst + e);

    float4  val;
    float4* out;
    if (j < 16) {
        val = __ldg(x4 + (size_t)s * 16 + j);
        out = g_agg4 + (size_t)d * 16 + j;
    } else {
        val = __ldg(v4 + (size_t)s * 48 + (j - 16));
        out = g_agg4 + (size_t)n_nodes * 16 + (size_t)d * 48 + (j - 16);
    }
    asm volatile("red.global.add.v4.f32 [%0], {%1,%2,%3,%4};"
                 :: "l"(out), "f"(val.x), "f"(val.y), "f"(val.z), "f"(val.w)
                 : "memory");
}

// ---------------------------------------------------------------------------
// Kernel 3: per-node projection.  One warp per node.  All 8 weight matrices
// (4 types x {W_s, W_v} x 64x64 f32 = 128 KB) staged in dynamic shared memory
// once per block; the node's aggregated row (256 floats) staged per warp.
// Lane handles output columns (2*lane, 2*lane+1) -> float2 conflict-free LDS
// and coalesced float2 stores.
// ---------------------------------------------------------------------------
__global__ void project_kernel(const int*   __restrict__ node_type,
                               const float* __restrict__ Ws,
                               const float* __restrict__ Wv,
                               float*       __restrict__ out,
                               int n_nodes) {
    extern __shared__ float sh[];
    float* sWs  = sh;                     // NT*4096 floats
    float* sWv  = sh + NT * 4096;         // NT*4096 floats
    float* sAgg = sh + 2 * NT * 4096;     // nwarps * 256 floats

    int tid = threadIdx.x;
    // Cooperative weight load (128 KB total) as float4
    const float4* Ws4 = (const float4*)Ws;
    const float4* Wv4 = (const float4*)Wv;
    for (int i = tid; i < NT * 1024; i += blockDim.x) {
        ((float4*)sWs)[i] = __ldg(Ws4 + i);
        ((float4*)sWv)[i] = __ldg(Wv4 + i);
    }
    __syncthreads();

    int warp   = tid >> 5;
    int lane   = tid & 31;
    int nwarps = blockDim.x >> 5;
    float* myAgg = sAgg + warp * 256;

    const float4* agg_s4 = g_agg4;                           // [n][16] float4
    const float4* agg_v4 = g_agg4 + (size_t)n_nodes * 16;    // [n][48] float4
    float* out_v = out + (size_t)n_nodes * 64;

    for (int n = blockIdx.x * nwarps + warp; n < n_nodes;
         n += gridDim.x * nwarps) {
        int t = __ldg(node_type + n);

        // Stage this node's 256-float aggregated row into shared
        #pragma unroll
        for (int q = lane; q < 64; q += 32) {
            float4 v;
            if (q < 16) v = __ldg(agg_s4 + (size_t)n * 16 + q);
            else        v = __ldg(agg_v4 + (size_t)n * 48 + (q - 16));
            ((float4*)myAgg)[q] = v;
        }
        __syncwarp();

        const float* ws = sWs + t * 4096;
        const float* wv = sWv + t * 4096;

        float2 accs  = make_float2(0.f, 0.f);
        float2 accv0 = make_float2(0.f, 0.f);
        float2 accv1 = make_float2(0.f, 0.f);
        float2 accv2 = make_float2(0.f, 0.f);

        #pragma unroll 8
        for (int k = 0; k < 64; k++) {
            float a_s  = myAgg[k];
            float a_v0 = myAgg[64  + k];
            float a_v1 = myAgg[128 + k];
            float a_v2 = myAgg[192 + k];
            float2 w_s = ((const float2*)(ws + k * 64))[lane];
            float2 w_v = ((const float2*)(wv + k * 64))[lane];
            accs.x  = fmaf(a_s,  w_s.x, accs.x);
            accs.y  = fmaf(a_s,  w_s.y, accs.y);
            accv0.x = fmaf(a_v0, w_v.x, accv0.x);
            accv0.y = fmaf(a_v0, w_v.y, accv0.y);
            accv1.x = fmaf(a_v1, w_v.x, accv1.x);
            accv1.y = fmaf(a_v1, w_v.y, accv1.y);
            accv2.x = fmaf(a_v2, w_v.x, accv2.x);
            accv2.y = fmaf(a_v2, w_v.y, accv2.y);
        }

        ((float2*)(out + (size_t)n * 64))[lane]          = accs;
        ((float2*)(out_v + (size_t)n * 192))[lane]       = accv0;
        ((float2*)(out_v + (size_t)n * 192 + 64))[lane]  = accv1;
        ((float2*)(out_v + (size_t)n * 192 + 128))[lane] = accv2;
        __syncwarp();   // protect myAgg before next iteration restages
    }
}

// ---------------------------------------------------------------------------
// Launch
// ---------------------------------------------------------------------------
extern "C" void kernel_launch(void* const* d_in, const int* in_sizes, int n_in,
                              void* d_out, int out_size) {
    const float* x   = (const float*)d_in[0];
    const float* vec = (const float*)d_in[1];
    const int*   nty = (const int*)d_in[2];
    const int*   src = (const int*)d_in[3];
    const int*   dst = (const int*)d_in[4];
    const float* Ws  = (const float*)d_in[5];
    const float* Wv  = (const float*)d_in[6];
    float* out = (float*)d_out;

    int n_nodes = in_sizes[2];
    int n_edges = in_sizes[3];

    // 1) zero the accumulator
    int n4 = n_nodes * 64;  // float4 count
    zero_agg_kernel<<<(n4 + 255) / 256, 256>>>(n4);

    // 2) scatter edges (one thread per float4 of message)
    int total = n_edges * 64;
    scatter_kernel<<<(total + 255) / 256, 256>>>(
        (const float4*)x, (const float4*)vec, src, dst, n_edges, n_nodes);

    // 3) per-node projection
    const int threads = 512;               // 16 warps
    const int nwarps  = threads / 32;
    size_t smem = (size_t)(2 * NT * 4096 + nwarps * 256) * sizeof(float); // 144 KB
    static bool attr_set = false;
    if (!attr_set) {
        cudaFuncSetAttribute(project_kernel,
                             cudaFuncAttributeMaxDynamicSharedMemorySize,
                             (int)smem);
        attr_set = true;
    }
    int grid = 296;  // ~2 waves at 1 block/SM (148-152 SMs), grid-stride covers rest
    project_kernel<<<grid, threads, smem>>>(nty, Ws, Wv, out, n_nodes);
}

// round 6
// speedup vs baseline: 1.0326x; 1.0326x over previous
#include <cuda_runtime.h>
#include <cuda_bf16.h>

// Problem constants (fixed by the dataset)
#define D 64
#define NT 4
#define N_NODES_MAX 50000

// Scratch accumulator: [agg_s: N*64 floats][agg_v: N*192 floats] = N*256 floats.
// float4-typed to guarantee 16B alignment for red.global.add.v4.f32.
__device__ float4 g_agg4[N_NODES_MAX * 64];   // 50000*256 floats = 51.2 MB

// ---------------------------------------------------------------------------
// Kernel 1: zero the accumulator
// ---------------------------------------------------------------------------
__global__ void zero_agg_kernel(int n4) {
    int i = blockIdx.x * blockDim.x + threadIdx.x;
    if (i < n4) g_agg4[i] = make_float4(0.f, 0.f, 0.f, 0.f);
}

// ---------------------------------------------------------------------------
// Kernel 2: edge scatter.  Each thread handles one float4 of one edge's
// message (64 float4s per edge: 16 for x-row, 48 for vec-rows) and issues a
// vectorized global reduction into the dst accumulator.
// ---------------------------------------------------------------------------
__global__ void scatter_kernel(const float4* __restrict__ x4,
                               const float4* __restrict__ v4,
                               const int*    __restrict__ src,
                               const int*    __restrict__ dst,
                               int n_edges, int n_nodes) {
    int i = blockIdx.x * blockDim.x + threadIdx.x;
    int total = n_edges * 64;
    if (i >= total) return;
    int e = i >> 6;
    int j = i & 63;
    int s = __ldg(src + e);
    int d = __ldg(dst + e);

    float4  val;
    float4* out;
    if (j < 16) {
        val = __ldg(x4 + (size_t)s * 16 + j);
        out = g_agg4 + (size_t)d * 16 + j;
    } else {
        val = __ldg(v4 + (size_t)s * 48 + (j - 16));
        out = g_agg4 + (size_t)n_nodes * 16 + (size_t)d * 48 + (j - 16);
    }
    asm volatile("red.global.add.v4.f32 [%0], {%1,%2,%3,%4};"
                 :: "l"(out), "f"(val.x), "f"(val.y), "f"(val.z), "f"(val.w)
                 : "memory");
}

// ---------------------------------------------------------------------------
// Kernel 3: per-node projection.  One warp per node.  All 8 weight matrices
// (4 types x {W_s, W_v} x 64x64 f32 = 128 KB) staged in dynamic shared memory
// once per block; the node's aggregated row (256 floats) staged per warp.
// Lane handles output columns (2*lane, 2*lane+1) -> float2 conflict-free LDS
// and coalesced float2 stores.
// ---------------------------------------------------------------------------
__global__ void project_kernel(const int*   __restrict__ node_type,
                               const float* __restrict__ Ws,
                               const float* __restrict__ Wv,
                               float*       __restrict__ out,
                               int n_nodes) {
    extern __shared__ float sh[];
    float* sWs  = sh;                     // NT*4096 floats
    float* sWv  = sh + NT * 4096;         // NT*4096 floats
    float* sAgg = sh + 2 * NT * 4096;     // nwarps * 256 floats

    int tid = threadIdx.x;
    // Cooperative weight load (128 KB total) as float4
    const float4* Ws4 = (const float4*)Ws;
    const float4* Wv4 = (const float4*)Wv;
    for (int i = tid; i < NT * 1024; i += blockDim.x) {
        ((float4*)sWs)[i] = __ldg(Ws4 + i);
        ((float4*)sWv)[i] = __ldg(Wv4 + i);
    }
    __syncthreads();

    int warp   = tid >> 5;
    int lane   = tid & 31;
    int nwarps = blockDim.x >> 5;
    float* myAgg = sAgg + warp * 256;

    const float4* agg_s4 = g_agg4;                           // [n][16] float4
    const float4* agg_v4 = g_agg4 + (size_t)n_nodes * 16;    // [n][48] float4
    float* out_v = out + (size_t)n_nodes * 64;

    for (int n = blockIdx.x * nwarps + warp; n < n_nodes;
         n += gridDim.x * nwarps) {
        int t = __ldg(node_type + n);

        // Stage this node's 256-float aggregated row into shared
        #pragma unroll
        for (int q = lane; q < 64; q += 32) {
            float4 v;
            if (q < 16) v = __ldg(agg_s4 + (size_t)n * 16 + q);
            else        v = __ldg(agg_v4 + (size_t)n * 48 + (q - 16));
            ((float4*)myAgg)[q] = v;
        }
        __syncwarp();

        const float* ws = sWs + t * 4096;
        const float* wv = sWv + t * 4096;

        float2 accs  = make_float2(0.f, 0.f);
        float2 accv0 = make_float2(0.f, 0.f);
        float2 accv1 = make_float2(0.f, 0.f);
        float2 accv2 = make_float2(0.f, 0.f);

        #pragma unroll 8
        for (int k = 0; k < 64; k++) {
            float a_s  = myAgg[k];
            float a_v0 = myAgg[64  + k];
            float a_v1 = myAgg[128 + k];
            float a_v2 = myAgg[192 + k];
            float2 w_s = ((const float2*)(ws + k * 64))[lane];
            float2 w_v = ((const float2*)(wv + k * 64))[lane];
            accs.x  = fmaf(a_s,  w_s.x, accs.x);
            accs.y  = fmaf(a_s,  w_s.y, accs.y);
            accv0.x = fmaf(a_v0, w_v.x, accv0.x);
            accv0.y = fmaf(a_v0, w_v.y, accv0.y);
            accv1.x = fmaf(a_v1, w_v.x, accv1.x);
            accv1.y = fmaf(a_v1, w_v.y, accv1.y);
            accv2.x = fmaf(a_v2, w_v.x, accv2.x);
            accv2.y = fmaf(a_v2, w_v.y, accv2.y);
        }

        ((float2*)(out + (size_t)n * 64))[lane]          = accs;
        ((float2*)(out_v + (size_t)n * 192))[lane]       = accv0;
        ((float2*)(out_v + (size_t)n * 192 + 64))[lane]  = accv1;
        ((float2*)(out_v + (size_t)n * 192 + 128))[lane] = accv2;
        __syncwarp();   // protect myAgg before next iteration restages
    }
}

// ---------------------------------------------------------------------------
// Launch
// ---------------------------------------------------------------------------
extern "C" void kernel_launch(void* const* d_in, const int* in_sizes, int n_in,
                              void* d_out, int out_size) {
    const float* x   = (const float*)d_in[0];
    const float* vec = (const float*)d_in[1];
    const int*   nty = (const int*)d_in[2];
    const int*   src = (const int*)d_in[3];
    const int*   dst = (const int*)d_in[4];
    const float* Ws  = (const float*)d_in[5];
    const float* Wv  = (const float*)d_in[6];
    float* out = (float*)d_out;

    int n_nodes = in_sizes[2];
    int n_edges = in_sizes[3];

    // 1) zero the accumulator
    int n4 = n_nodes * 64;  // float4 count
    zero_agg_kernel<<<(n4 + 255) / 256, 256>>>(n4);

    // 2) scatter edges (one thread per float4 of message)
    int total = n_edges * 64;
    scatter_kernel<<<(total + 255) / 256, 256>>>(
        (const float4*)x, (const float4*)vec, src, dst, n_edges, n_nodes);

    // 3) per-node projection
    const int threads = 512;               // 16 warps
    const int nwarps  = threads / 32;
    size_t smem = (size_t)(2 * NT * 4096 + nwarps * 256) * sizeof(float); // 144 KB
    static bool attr_set = false;
    if (!attr_set) {
        cudaFuncSetAttribute(project_kernel,
                             cudaFuncAttributeMaxDynamicSharedMemorySize,
                             (int)smem);
        attr_set = true;
    }
    int grid = 296;  // ~2 waves at 1 block/SM (148-152 SMs), grid-stride covers rest
    project_kernel<<<grid, threads, smem>>>(nty, Ws, Wv, out, n_nodes);
}

// round 7
// speedup vs baseline: 1.3998x; 1.3556x over previous
#include <cuda_runtime.h>
#include <cuda_bf16.h>

#define D 64
#define NT 4
#define N_NODES_MAX 50000
#define N_EDGES_MAX 800000

// CSR scratch (static __device__ arrays; ~3.7 MB total)
__device__ int g_deg[N_NODES_MAX];       // in-degree histogram
__device__ int g_off[N_NODES_MAX + 1];   // CSR row offsets
__device__ int g_cur[N_NODES_MAX];       // fill cursors
__device__ int g_ssrc[N_EDGES_MAX];      // src ids bucketed by dst

// ---------------------------------------------------------------------------
// 1) zero degree counters
// ---------------------------------------------------------------------------
__global__ void zero_deg_kernel(int n) {
    int i = blockIdx.x * blockDim.x + threadIdx.x;
    if (i < n) g_deg[i] = 0;
}

// ---------------------------------------------------------------------------
// 2) in-degree histogram
// ---------------------------------------------------------------------------
__global__ void hist_kernel(const int* __restrict__ dst, int n_edges) {
    int e = blockIdx.x * blockDim.x + threadIdx.x;
    if (e < n_edges) atomicAdd(&g_deg[dst[e]], 1);
}

// ---------------------------------------------------------------------------
// 3) single-block exclusive scan -> offsets + cursors
// ---------------------------------------------------------------------------
__global__ void scan_kernel(int n_nodes) {
    __shared__ int part[1024];
    int tid = threadIdx.x;
    int chunk = (n_nodes + 1023) / 1024;
    int begin = tid * chunk;
    int endi  = min(begin + chunk, n_nodes);

    int s = 0;
    for (int i = begin; i < endi; i++) s += g_deg[i];
    part[tid] = s;
    __syncthreads();

    // Hillis-Steele inclusive scan over 1024 partials
    for (int off = 1; off < 1024; off <<= 1) {
        int v = (tid >= off) ? part[tid - off] : 0;
        __syncthreads();
        part[tid] += v;
        __syncthreads();
    }

    int prefix = (tid > 0) ? part[tid - 1] : 0;
    for (int i = begin; i < endi; i++) {
        int d = g_deg[i];
        g_off[i] = prefix;
        g_cur[i] = prefix;
        prefix += d;
    }
    if (tid == 1023) g_off[n_nodes] = part[1023];
}

// ---------------------------------------------------------------------------
// 4) bucket fill: src ids grouped by dst
// ---------------------------------------------------------------------------
__global__ void fill_kernel(const int* __restrict__ src,
                            const int* __restrict__ dst, int n_edges) {
    int e = blockIdx.x * blockDim.x + threadIdx.x;
    if (e < n_edges) {
        int pos = atomicAdd(&g_cur[dst[e]], 1);
        g_ssrc[pos] = src[e];
    }
}

// ---------------------------------------------------------------------------
// 5) fused gather + per-type projection.  Warp per node.
//    - weights (4 types x {W_s,W_v} x 64x64 f32 = 128 KB) staged per block
//    - per-edge: each lane accumulates 2 float4 of the src node's 256-float
//      row (j = lane and j = 32+lane) into registers -- no atomics
//    - agg row staged into shared, then 4 matvecs (lane = 2 output cols)
// ---------------------------------------------------------------------------
__global__ void __launch_bounds__(1024, 1)
fused_kernel(const int*    __restrict__ node_type,
             const float*  __restrict__ Ws,
             const float*  __restrict__ Wv,
             const float4* __restrict__ x4,
             const float4* __restrict__ v4,
             float*        __restrict__ out,
             int n_nodes) {
    extern __shared__ float sh[];
    float* sWs  = sh;                     // NT*4096 floats
    float* sWv  = sh + NT * 4096;         // NT*4096 floats
    float* sAgg = sh + 2 * NT * 4096;     // nwarps * 256 floats

    int tid = threadIdx.x;
    const float4* Ws4 = (const float4*)Ws;
    const float4* Wv4 = (const float4*)Wv;
    for (int i = tid; i < NT * 1024; i += blockDim.x) {
        ((float4*)sWs)[i] = __ldg(Ws4 + i);
        ((float4*)sWv)[i] = __ldg(Wv4 + i);
    }
    __syncthreads();

    int warp   = tid >> 5;
    int lane   = tid & 31;
    int nwarps = blockDim.x >> 5;
    float* myAgg = sAgg + warp * 256;
    float* out_v = out + (size_t)n_nodes * 64;

    for (int n = blockIdx.x * nwarps + warp; n < n_nodes;
         n += gridDim.x * nwarps) {
        int beg = __ldg(g_off + n);
        int end = __ldg(g_off + n + 1);

        // --- gather phase: accumulate agg row in registers ---
        // lane handles float4 slots j0=lane (x for lane<16, vec otherwise)
        // and j1=32+lane (vec)
        float4 acc0 = make_float4(0.f, 0.f, 0.f, 0.f);
        float4 acc1 = make_float4(0.f, 0.f, 0.f, 0.f);

        #pragma unroll 4
        for (int e = beg; e < end; e++) {
            int s = __ldg(g_ssrc + e);
            const float4* p0 = (lane < 16) ? (x4 + (size_t)s * 16 + lane)
                                           : (v4 + (size_t)s * 48 + (lane - 16));
            float4 a = __ldg(p0);
            float4 b = __ldg(v4 + (size_t)s * 48 + 16 + lane);
            acc0.x += a.x; acc0.y += a.y; acc0.z += a.z; acc0.w += a.w;
            acc1.x += b.x; acc1.y += b.y; acc1.z += b.z; acc1.w += b.w;
        }

        // --- stage agg row to shared ---
        ((float4*)myAgg)[lane]      = acc0;
        ((float4*)myAgg)[32 + lane] = acc1;
        __syncwarp();

        // --- projection: 4 matvecs against type-t weights ---
        int t = __ldg(node_type + n);
        const float* ws = sWs + t * 4096;
        const float* wv = sWv + t * 4096;

        float2 accs  = make_float2(0.f, 0.f);
        float2 accv0 = make_float2(0.f, 0.f);
        float2 accv1 = make_float2(0.f, 0.f);
        float2 accv2 = make_float2(0.f, 0.f);

        #pragma unroll 8
        for (int k = 0; k < 64; k++) {
            float a_s  = myAgg[k];
            float a_v0 = myAgg[64  + k];
            float a_v1 = myAgg[128 + k];
            float a_v2 = myAgg[192 + k];
            float2 w_s = ((const float2*)(ws + k * 64))[lane];
            float2 w_v = ((const float2*)(wv + k * 64))[lane];
            accs.x  = fmaf(a_s,  w_s.x, accs.x);
            accs.y  = fmaf(a_s,  w_s.y, accs.y);
            accv0.x = fmaf(a_v0, w_v.x, accv0.x);
            accv0.y = fmaf(a_v0, w_v.y, accv0.y);
            accv1.x = fmaf(a_v1, w_v.x, accv1.x);
            accv1.y = fmaf(a_v1, w_v.y, accv1.y);
            accv2.x = fmaf(a_v2, w_v.x, accv2.x);
            accv2.y = fmaf(a_v2, w_v.y, accv2.y);
        }

        ((float2*)(out + (size_t)n * 64))[lane]          = accs;
        ((float2*)(out_v + (size_t)n * 192))[lane]       = accv0;
        ((float2*)(out_v + (size_t)n * 192 + 64))[lane]  = accv1;
        ((float2*)(out_v + (size_t)n * 192 + 128))[lane] = accv2;
        __syncwarp();   // protect myAgg before next node restages
    }
}

// ---------------------------------------------------------------------------
// Launch
// ---------------------------------------------------------------------------
extern "C" void kernel_launch(void* const* d_in, const int* in_sizes, int n_in,
                              void* d_out, int out_size) {
    const float* x   = (const float*)d_in[0];
    const float* vec = (const float*)d_in[1];
    const int*   nty = (const int*)d_in[2];
    const int*   src = (const int*)d_in[3];
    const int*   dst = (const int*)d_in[4];
    const float* Ws  = (const float*)d_in[5];
    const float* Wv  = (const float*)d_in[6];
    float* out = (float*)d_out;

    int n_nodes = in_sizes[2];
    int n_edges = in_sizes[3];

    // CSR build
    zero_deg_kernel<<<(n_nodes + 255) / 256, 256>>>(n_nodes);
    hist_kernel<<<(n_edges + 255) / 256, 256>>>(dst, n_edges);
    scan_kernel<<<1, 1024>>>(n_nodes);
    fill_kernel<<<(n_edges + 255) / 256, 256>>>(src, dst, n_edges);

    // Fused gather + project: 1024 threads (32 warps), persistent 1-wave grid
    const int threads = 1024;
    const int nwarps  = threads / 32;
    size_t smem = (size_t)(2 * NT * 4096 + nwarps * 256) * sizeof(float); // 160 KB
    static bool attr_set = false;
    if (!attr_set) {
        cudaFuncSetAttribute(fused_kernel,
                             cudaFuncAttributeMaxDynamicSharedMemorySize,
                             (int)smem);
        attr_set = true;
    }
    fused_kernel<<<148, threads, smem>>>(
        nty, Ws, Wv, (const float4*)x, (const float4*)vec, out, n_nodes);
}